// round 1
// baseline (speedup 1.0000x reference)
#include <cuda_runtime.h>

// DisplaceChannel + learnable-offset Gaussian depthwise conv, fused.
//
// inp:    (B=16, C=192, H=128, W=128) fp32
// offset: (P=48, 2) fp32, layout [x, y]
// out:    same shape as inp
//
// out(b,c,y,x) = sum_{ky,kx} w[p][ky][kx] * shifted(y+ky-1, x+kx-1)
//   shifted(yy,xx) = inp(b,c, yy-Ry, xx-Rx) if all of yy,xx,yy-Ry,xx-Rx in range, else 0
//   (Rx,Ry) = round-half-even(offset[p])  [matches jnp.round via rintf/RN]
//   w = normalized Gaussian of fractional residual, sigma=0.5.

namespace {
constexpr int H = 128;
constexpr int W = 128;
constexpr int C = 192;      // channels = 48 positions * 4 channels/pos
constexpr int TH = 16;      // output rows per block tile
constexpr int SW = 136;     // shared row stride (floats): 4 left pad + 130 + pad
constexpr float INV_2SIG2 = 2.0f;  // 1/(2*0.5^2)
}

__global__ __launch_bounds__(256)
void displace_lo_kernel(const float* __restrict__ inp,
                        const float* __restrict__ offset,
                        float* __restrict__ out) {
    __shared__ __align__(16) float sm[TH + 2][SW];

    const int bid   = blockIdx.x;
    const int tile  = bid & 7;            // 8 row-tiles per 128-row plane
    const int plane = bid >> 3;           // b*C + c
    const int p     = (plane % C) >> 2;   // position index (cpp = 4)

    // ---- per-position Gaussian weights (computed redundantly; tiny) ----
    const float ox = offset[2 * p + 0];
    const float oy = offset[2 * p + 1];
    const float rx = rintf(ox), ry = rintf(oy);   // round-half-even == jnp.round
    const int   Rx = (int)rx,  Ry = (int)ry;
    const float dx = ox - rx,  dy = oy - ry;

    float w[3][3];
    float s = 0.0f;
#pragma unroll
    for (int ky = 0; ky < 3; ++ky) {
#pragma unroll
        for (int kx = 0; kx < 3; ++kx) {
            const float fx = (float)(kx - 1) + dx;
            const float fy = (float)(ky - 1) + dy;
            const float e  = expf(-(fx * fx + fy * fy) * INV_2SIG2);
            w[ky][kx] = e;
            s += e;
        }
    }
    const float invs = 1.0f / s;
#pragma unroll
    for (int ky = 0; ky < 3; ++ky)
#pragma unroll
        for (int kx = 0; kx < 3; ++kx) w[ky][kx] *= invs;

    const float* __restrict__ ip = inp + (size_t)plane * (H * W);
    float* __restrict__       op = out + (size_t)plane * (H * W);
    const int y0  = tile * TH;
    const int tid = threadIdx.x;

    // ---- stage shifted tile (with conv halo rows/cols) into shared ----
    // shared col index = logical col c + 4; rows r=0..17 map to gy = y0-1+r.
    for (int idx = tid; idx < (TH + 2) * W; idx += 256) {
        const int r  = idx >> 7;          // /W
        const int c  = idx & (W - 1);
        const int gy = y0 - 1 + r;        // row in the shifted (pre-conv) image
        const int sy = gy - Ry;           // source row in inp
        const int sx = c  - Rx;           // source col in inp
        float v = 0.0f;
        if ((unsigned)gy < (unsigned)H && (unsigned)sy < (unsigned)H &&
            (unsigned)sx < (unsigned)W)
            v = __ldg(ip + sy * W + sx);
        sm[r][c + 4] = v;
    }
    // conv zero-pad halo columns (c = -1 and c = W)
    if (tid < TH + 2) {
        sm[tid][3]     = 0.0f;
        sm[tid][W + 4] = 0.0f;
    }
    __syncthreads();

    // ---- compute: each thread -> 2 output rows x 4 cols (float4 stores) ----
    const int rp    = tid >> 5;        // row-pair 0..7
    const int lane  = tid & 31;        // 32 lanes cover W/4 = 32 quads
    const int x4    = lane << 2;       // output col base
    const int rbase = rp << 1;         // local output row base (0,2,..,14)

    float a00 = 0.f, a01 = 0.f, a02 = 0.f, a03 = 0.f;  // out row rbase
    float a10 = 0.f, a11 = 0.f, a12 = 0.f, a13 = 0.f;  // out row rbase+1

#pragma unroll
    for (int rr = 0; rr < 4; ++rr) {
        // shared row rbase+rr corresponds to shifted-image row y0+rbase+rr-1
        const float* row = &sm[rbase + rr][x4];   // idx x4 <-> col x4-4
        const float4 va = *(const float4*)(row);      // cols x4-4 .. x4-1
        const float4 vb = *(const float4*)(row + 4);  // cols x4   .. x4+3
        const float4 vc = *(const float4*)(row + 8);  // cols x4+4 .. x4+7
        const float e0 = va.w, e1 = vb.x, e2 = vb.y,
                    e3 = vb.z, e4 = vb.w, e5 = vc.x;  // cols x4-1 .. x4+4

        if (rr < 3) {           // contributes to out row rbase with ky = rr
            const float k0 = w[rr][0], k1 = w[rr][1], k2 = w[rr][2];
            a00 += k0 * e0 + k1 * e1 + k2 * e2;
            a01 += k0 * e1 + k1 * e2 + k2 * e3;
            a02 += k0 * e2 + k1 * e3 + k2 * e4;
            a03 += k0 * e3 + k1 * e4 + k2 * e5;
        }
        if (rr >= 1) {          // contributes to out row rbase+1 with ky = rr-1
            const float k0 = w[rr - 1][0], k1 = w[rr - 1][1], k2 = w[rr - 1][2];
            a10 += k0 * e0 + k1 * e1 + k2 * e2;
            a11 += k0 * e1 + k1 * e2 + k2 * e3;
            a12 += k0 * e2 + k1 * e3 + k2 * e4;
            a13 += k0 * e3 + k1 * e4 + k2 * e5;
        }
    }

    *(float4*)(op + (y0 + rbase)     * W + x4) = make_float4(a00, a01, a02, a03);
    *(float4*)(op + (y0 + rbase + 1) * W + x4) = make_float4(a10, a11, a12, a13);
}

extern "C" void kernel_launch(void* const* d_in, const int* in_sizes, int n_in,
                              void* d_out, int out_size) {
    const float* inp = (const float*)d_in[0];
    const float* off = (const float*)d_in[1];
    float*       out = (float*)d_out;

    const int planes = in_sizes[0] / (H * W);     // B*C = 3072
    const int blocks = planes * (H / TH);         // 24576
    displace_lo_kernel<<<blocks, 256>>>(inp, off, out);
}

// round 10
// speedup vs baseline: 1.7927x; 1.7927x over previous
#include <cuda_runtime.h>

// Fused DisplaceChannel (integer shift, zero fill) + separable Gaussian 3x3
// depthwise conv, register-pipelined, no shared memory, 2 rows/iteration for ILP.
//
// inp:    (B=16, C=192, H=128, W=128) fp32
// offset: (P=48, 2) fp32, layout [x, y]
//
// out(y,x) = sum_{ky,kx} wy[ky]*wx[kx] * shifted(y+ky-1, x+kx-1)
//   shifted(yy,xx) = inp(yy-Ry, xx-Rx) if yy,xx,yy-Ry,xx-Rx all in range else 0
//   (Rx,Ry) = round-half-even(offset)   [rintf == jnp.round]
//   wx,wy   = normalized 1D Gaussians of the fractional residual (sigma=0.5);
//             the 2D kernel and its normalizer factorize exactly.

namespace {
constexpr int H = 128;
constexpr int W = 128;
constexpr int C = 192;            // 48 positions * 4 channels each
constexpr int ROWS_PER_WARP = 16; // 8 warps x 16 rows = 128-row plane
}

__global__ __launch_bounds__(256)
void displace_lo_kernel(const float* __restrict__ inp,
                        const float* __restrict__ offset,
                        float* __restrict__ out) {
    const int plane = blockIdx.x;            // b*C + c
    const int p     = (plane % C) >> 2;      // position (cpp = 4)
    const int wid   = threadIdx.x >> 5;
    const int lane  = threadIdx.x & 31;
    const int x4    = lane << 2;             // output col base (multiple of 4)

    // ---- separable Gaussian weights from the fractional residual ----
    const float ox = offset[2 * p + 0];
    const float oy = offset[2 * p + 1];
    const float rx = rintf(ox), ry = rintf(oy);   // round-half-even == jnp.round
    const int   Rx = (int)rx,  Ry = (int)ry;
    const float dx = ox - rx,  dy = oy - ry;

    float wx0, wx1, wx2, wy0, wy1, wy2;
    {
        const float fx0 = -1.f + dx, fx1 = dx, fx2 = 1.f + dx;
        const float fy0 = -1.f + dy, fy1 = dy, fy2 = 1.f + dy;
        // 1/(2*sigma^2) = 2 for sigma = 0.5
        const float ex0 = expf(-2.f * fx0 * fx0);
        const float ex1 = expf(-2.f * fx1 * fx1);
        const float ex2 = expf(-2.f * fx2 * fx2);
        const float ey0 = expf(-2.f * fy0 * fy0);
        const float ey1 = expf(-2.f * fy1 * fy1);
        const float ey2 = expf(-2.f * fy2 * fy2);
        const float isx = 1.f / (ex0 + ex1 + ex2);
        const float isy = 1.f / (ey0 + ey1 + ey2);
        wx0 = ex0 * isx; wx1 = ex1 * isx; wx2 = ex2 * isx;
        wy0 = ey0 * isy; wy1 = ey1 * isy; wy2 = ey2 * isy;
    }

    const float* __restrict__ ip = inp + (size_t)plane * (H * W);
    float* __restrict__       op = out + (size_t)plane * (H * W);
    // source-row pointer pre-shifted by the integer displacement
    const float* __restrict__ ipsh = ip - (ptrdiff_t)Ry * W;

    const int  r0      = wid * ROWS_PER_WARP;
    const bool aligned = ((Rx & 3) == 0);    // block-uniform branch
    const int  cA      = x4 - Rx;            // aligned-case source col base

    // Load shifted row y (zeros for conv-pad rows / displaced-out pixels),
    // then horizontal 3-tap pass. Lane edges supply the x = -1 / W zero pad.
    auto hrow = [&](int y) -> float4 {
        float4 v = make_float4(0.f, 0.f, 0.f, 0.f);
        const int ys = y - Ry;
        if (((unsigned)y < (unsigned)H) & ((unsigned)ys < (unsigned)H)) {
            const float* src = ipsh + y * W;
            if (aligned) {
                if ((unsigned)cA <= (unsigned)(W - 4))   // all-in or all-out
                    v = *(const float4*)(src + cA);
            } else {
                float* vf = (float*)&v;
#pragma unroll
                for (int j = 0; j < 4; ++j) {
                    const int c = x4 + j - Rx;
                    if ((unsigned)c < (unsigned)W) vf[j] = src[c];
                }
            }
        }
        float el = __shfl_up_sync(0xffffffffu, v.w, 1);
        float er = __shfl_down_sync(0xffffffffu, v.x, 1);
        if (lane == 0)  el = 0.f;
        if (lane == 31) er = 0.f;
        float4 h;
        h.x = wx0 * el  + wx1 * v.x + wx2 * v.y;
        h.y = wx0 * v.x + wx1 * v.y + wx2 * v.z;
        h.z = wx0 * v.y + wx1 * v.z + wx2 * v.w;
        h.w = wx0 * v.z + wx1 * v.w + wx2 * er;
        return h;
    };

    // ---- vertical 3-tap, 2 output rows per iteration (2 independent
    // LDG+SHFL chains in flight so latency of one overlaps FMAs of the other) ----
    float4 hA = hrow(r0 - 1);
    float4 hB = hrow(r0);

#pragma unroll
    for (int i = 0; i < ROWS_PER_WARP; i += 2) {
        const float4 hC = hrow(r0 + 1 + i);   // independent of hD
        const float4 hD = hrow(r0 + 2 + i);   // independent of hC

        float4 o0, o1;
        o0.x = wy0 * hA.x + wy1 * hB.x + wy2 * hC.x;
        o0.y = wy0 * hA.y + wy1 * hB.y + wy2 * hC.y;
        o0.z = wy0 * hA.z + wy1 * hB.z + wy2 * hC.z;
        o0.w = wy0 * hA.w + wy1 * hB.w + wy2 * hC.w;

        o1.x = wy0 * hB.x + wy1 * hC.x + wy2 * hD.x;
        o1.y = wy0 * hB.y + wy1 * hC.y + wy2 * hD.y;
        o1.z = wy0 * hB.z + wy1 * hC.z + wy2 * hD.z;
        o1.w = wy0 * hB.w + wy1 * hC.w + wy2 * hD.w;

        *(float4*)(op + (r0 + i)     * W + x4) = o0;
        *(float4*)(op + (r0 + i + 1) * W + x4) = o1;

        hA = hC;
        hB = hD;
    }
}

extern "C" void kernel_launch(void* const* d_in, const int* in_sizes, int n_in,
                              void* d_out, int out_size) {
    const float* inp = (const float*)d_in[0];
    const float* off = (const float*)d_in[1];
    float*       out = (float*)d_out;

    const int planes = in_sizes[0] / (H * W);   // B*C = 3072
    displace_lo_kernel<<<planes, 256>>>(inp, off, out);
}

// round 14
// speedup vs baseline: 2.3253x; 1.2970x over previous
#include <cuda_runtime.h>

// Fused DisplaceChannel (integer shift, zero fill) + separable Gaussian 3x3
// depthwise conv, register-pipelined, no shared memory, 4 rows/iteration
// (4 independent LDG+SHFL chains in flight), streaming (__stcs) stores.
//
// inp:    (B=16, C=192, H=128, W=128) fp32
// offset: (P=48, 2) fp32, layout [x, y]
//
// out(y,x) = sum_{ky,kx} wy[ky]*wx[kx] * shifted(y+ky-1, x+kx-1)
//   shifted(yy,xx) = inp(yy-Ry, xx-Rx) if yy,xx,yy-Ry,xx-Rx all in range else 0
//   (Rx,Ry) = round-half-even(offset)   [rintf == jnp.round]
//   wx,wy   = normalized 1D Gaussians of the fractional residual (sigma=0.5);
//             the 2D kernel and its normalizer factorize exactly.

namespace {
constexpr int H = 128;
constexpr int W = 128;
constexpr int C = 192;            // 48 positions * 4 channels each
constexpr int ROWS_PER_WARP = 16; // 8 warps x 16 rows = 128-row plane
}

__global__ __launch_bounds__(256)
void displace_lo_kernel(const float* __restrict__ inp,
                        const float* __restrict__ offset,
                        float* __restrict__ out) {
    const int plane = blockIdx.x;            // b*C + c
    const int p     = (plane % C) >> 2;      // position (cpp = 4)
    const int wid   = threadIdx.x >> 5;
    const int lane  = threadIdx.x & 31;
    const int x4    = lane << 2;             // output col base (multiple of 4)

    // ---- separable Gaussian weights from the fractional residual ----
    const float ox = offset[2 * p + 0];
    const float oy = offset[2 * p + 1];
    const float rx = rintf(ox), ry = rintf(oy);   // round-half-even == jnp.round
    const int   Rx = (int)rx,  Ry = (int)ry;
    const float dx = ox - rx,  dy = oy - ry;

    float wx0, wx1, wx2, wy0, wy1, wy2;
    {
        const float fx0 = -1.f + dx, fx1 = dx, fx2 = 1.f + dx;
        const float fy0 = -1.f + dy, fy1 = dy, fy2 = 1.f + dy;
        // 1/(2*sigma^2) = 2 for sigma = 0.5
        const float ex0 = expf(-2.f * fx0 * fx0);
        const float ex1 = expf(-2.f * fx1 * fx1);
        const float ex2 = expf(-2.f * fx2 * fx2);
        const float ey0 = expf(-2.f * fy0 * fy0);
        const float ey1 = expf(-2.f * fy1 * fy1);
        const float ey2 = expf(-2.f * fy2 * fy2);
        const float isx = 1.f / (ex0 + ex1 + ex2);
        const float isy = 1.f / (ey0 + ey1 + ey2);
        wx0 = ex0 * isx; wx1 = ex1 * isx; wx2 = ex2 * isx;
        wy0 = ey0 * isy; wy1 = ey1 * isy; wy2 = ey2 * isy;
    }

    const float* __restrict__ ip = inp + (size_t)plane * (H * W);
    float* __restrict__       op = out + (size_t)plane * (H * W);
    // source-row pointer pre-shifted by the integer displacement
    const float* __restrict__ ipsh = ip - (ptrdiff_t)Ry * W;

    const int  r0      = wid * ROWS_PER_WARP;
    const bool aligned = ((Rx & 3) == 0);    // block-uniform branch
    const int  cA      = x4 - Rx;            // aligned-case source col base

    // Raw shifted-row load (zeros for conv-pad rows / displaced-out pixels).
    auto vload = [&](int y) -> float4 {
        float4 v = make_float4(0.f, 0.f, 0.f, 0.f);
        const int ys = y - Ry;
        if (((unsigned)y < (unsigned)H) & ((unsigned)ys < (unsigned)H)) {
            const float* src = ipsh + y * W;
            if (aligned) {
                if ((unsigned)cA <= (unsigned)(W - 4))   // all-in or all-out
                    v = *(const float4*)(src + cA);
            } else {
                float* vf = (float*)&v;
#pragma unroll
                for (int j = 0; j < 4; ++j) {
                    const int c = x4 + j - Rx;
                    if ((unsigned)c < (unsigned)W) vf[j] = src[c];
                }
            }
        }
        return v;
    };

    // Horizontal 3-tap; lane edges supply the x = -1 / W zero pad.
    auto hpass = [&](float4 v) -> float4 {
        float el = __shfl_up_sync(0xffffffffu, v.w, 1);
        float er = __shfl_down_sync(0xffffffffu, v.x, 1);
        if (lane == 0)  el = 0.f;
        if (lane == 31) er = 0.f;
        float4 h;
        h.x = wx0 * el  + wx1 * v.x + wx2 * v.y;
        h.y = wx0 * v.x + wx1 * v.y + wx2 * v.z;
        h.z = wx0 * v.y + wx1 * v.z + wx2 * v.w;
        h.w = wx0 * v.z + wx1 * v.w + wx2 * er;
        return h;
    };

    // ---- vertical 3-tap, 4 output rows per iteration: 4 independent
    // loads issued back-to-back, then 4 h-passes, then 4 v-passes. ----
    float4 hA = hpass(vload(r0 - 1));
    float4 hB = hpass(vload(r0));

#pragma unroll
    for (int i = 0; i < ROWS_PER_WARP; i += 4) {
        // front-batched independent loads (MLP = 4)
        const float4 vC = vload(r0 + 1 + i);
        const float4 vD = vload(r0 + 2 + i);
        const float4 vE = vload(r0 + 3 + i);
        const float4 vF = vload(r0 + 4 + i);

        const float4 hC = hpass(vC);
        const float4 hD = hpass(vD);
        const float4 hE = hpass(vE);
        const float4 hF = hpass(vF);

        float4 o0, o1, o2, o3;
        o0.x = wy0 * hA.x + wy1 * hB.x + wy2 * hC.x;
        o0.y = wy0 * hA.y + wy1 * hB.y + wy2 * hC.y;
        o0.z = wy0 * hA.z + wy1 * hB.z + wy2 * hC.z;
        o0.w = wy0 * hA.w + wy1 * hB.w + wy2 * hC.w;

        o1.x = wy0 * hB.x + wy1 * hC.x + wy2 * hD.x;
        o1.y = wy0 * hB.y + wy1 * hC.y + wy2 * hD.y;
        o1.z = wy0 * hB.z + wy1 * hC.z + wy2 * hD.z;
        o1.w = wy0 * hB.w + wy1 * hC.w + wy2 * hD.w;

        o2.x = wy0 * hC.x + wy1 * hD.x + wy2 * hE.x;
        o2.y = wy0 * hC.y + wy1 * hD.y + wy2 * hE.y;
        o2.z = wy0 * hC.z + wy1 * hD.z + wy2 * hE.z;
        o2.w = wy0 * hC.w + wy1 * hD.w + wy2 * hE.w;

        o3.x = wy0 * hD.x + wy1 * hE.x + wy2 * hF.x;
        o3.y = wy0 * hD.y + wy1 * hE.y + wy2 * hF.y;
        o3.z = wy0 * hD.z + wy1 * hE.z + wy2 * hF.z;
        o3.w = wy0 * hD.w + wy1 * hE.w + wy2 * hF.w;

        // streaming stores: output is write-once, keep L2 for the read stream
        float4* orow = (float4*)(op + (r0 + i) * W + x4);
        __stcs(orow,                 o0);
        __stcs((float4*)((float*)orow + W),     o1);
        __stcs((float4*)((float*)orow + 2 * W), o2);
        __stcs((float4*)((float*)orow + 3 * W), o3);

        hA = hE;
        hB = hF;
    }
}

extern "C" void kernel_launch(void* const* d_in, const int* in_sizes, int n_in,
                              void* d_out, int out_size) {
    const float* inp = (const float*)d_in[0];
    const float* off = (const float*)d_in[1];
    float*       out = (float*)d_out;

    const int planes = in_sizes[0] / (H * W);   // B*C = 3072
    displace_lo_kernel<<<planes, 256>>>(inp, off, out);
}